// round 13
// baseline (speedup 1.0000x reference)
#include <cuda_runtime.h>
#include <cstdint>

// LIF-MC-Refrac (R13): all-tensor + exact fixup.
//  K_reset : zero the suspect counter.
//  K2 i-path : TF32 mma.sync (R11 layout, 256 thr) -> i.
//  K1 coupling: tf32x3 mma.sync (hi*hi+hi*lo+lo*hi) -> z,v,rho; flags elements
//               with |v_dec-1| < EPS into a device list.
//  K_fixup : recompute flagged couplings exactly (serial ascending-k fp32 FMA,
//            the ordering proven 0-flip in R1) and rewrite z/v/rho.

namespace {
constexpr int Bd = 4096;
constexpr int Hd = 2048;
constexpr int Kd = 2048;

constexpr int BM = 128, BN = 128, BK = 16;
constexpr int SSTR = BK + 4;

constexpr float DT_TAU_MEM = 0.1f;
constexpr float DT_TAU_SYN = 0.2f;
constexpr float V_TH_C     = 1.0f;
constexpr float RHO_RST    = 5.0f;

constexpr float EPS_FIX    = 4e-3f;
constexpr int   MAX_SUSP   = 1 << 20;
}

__device__ int g_susp_count;
__device__ int g_susp_list[MAX_SUSP];

__device__ __forceinline__ uint32_t f2tf32(float x) {
    uint32_t r;
    asm("cvt.rna.tf32.f32 %0, %1;" : "=r"(r) : "f"(x));
    return r;
}

__device__ __forceinline__ void mma_tf32(float& c0, float& c1, float& c2, float& c3,
                                         uint32_t a0, uint32_t a1, uint32_t a2, uint32_t a3,
                                         uint32_t b0, uint32_t b1)
{
    asm volatile(
        "mma.sync.aligned.m16n8k8.row.col.f32.tf32.tf32.f32 "
        "{%0,%1,%2,%3},{%4,%5,%6,%7},{%8,%9},{%0,%1,%2,%3};"
        : "+f"(c0), "+f"(c1), "+f"(c2), "+f"(c3)
        : "r"(a0), "r"(a1), "r"(a2), "r"(a3), "r"(b0), "r"(b1));
}

__device__ __forceinline__ void lif_elem(float v, float i, float rho, float couple,
                                         float& z_out, float& v_out, float& rho_out)
{
    float dv    = DT_TAU_MEM * ((0.0f - v) + i);
    float v_dec = (v + dv) + couple;
    float z     = (v_dec - V_TH_C) > 0.0f ? 1.0f : 0.0f;
    float v_new = (1.0f - z) * v_dec;
    float mask  = rho > 0.0f ? 1.0f : 0.0f;
    v_new = (1.0f - mask) * v_new + mask * v;
    z     = (1.0f - mask) * z;
    rho_out = (1.0f - z) * fmaxf(rho - mask, 0.0f) + z * RHO_RST;
    z_out = z;
    v_out = v_new;
}

// =============== K_reset ======================================================
__global__ void reset_kernel() {
    if (threadIdx.x == 0) g_susp_count = 0;
}

// =============== K1: tf32x3 coupling + suspect flagging ======================
// R11 conflict-free k-position map: pos(k)=2f(a,c)+b, f0=[0,2,1,3], f1=[5,7,4,6]
__global__ void __launch_bounds__(256, 2) coupling_tc_kernel(
    const float* __restrict__ A0, const float* __restrict__ W0,
    const float* __restrict__ vin, const float* __restrict__ iin,
    const float* __restrict__ rhoin,
    float* __restrict__ out_z, float* __restrict__ out_v, float* __restrict__ out_rho)
{
    __shared__ uint32_t Ahi[BM * SSTR];
    __shared__ uint32_t Alo[BM * SSTR];
    __shared__ uint32_t Bhi[BN * SSTR];
    __shared__ uint32_t Blo[BN * SSTR];

    const int bid = blockIdx.x;
    const int bx = bid & 15;
    const int by = bid >> 4;

    const int tid  = threadIdx.x;
    const int warp = tid >> 5;
    const int lane = tid & 31;
    const int g    = lane >> 2;
    const int q    = lane & 3;
    const int wM   = warp >> 2;
    const int wN   = warp & 3;

    const int loadRow = tid >> 2;
    const int loadK   = (tid & 3) << 2;
    const int t       = tid & 3;
    const int ta_     = t >> 1;
    const int tb_     = t & 1;

    const int d0 = (ta_ ? 10 : 0) + tb_;
    const int d1 = (ta_ ? 14 : 4) + tb_;
    const int d2 = (ta_ ?  8 : 2) + tb_;
    const int d3 = (ta_ ? 12 : 6) + tb_;

    const int B0q  = ((q & 1) << 2) | (q & 2);
    const int off0 = B0q;
    const int off1 = 8 + (B0q ^ 2);

    float acc[4][4][4];
#pragma unroll
    for (int mt = 0; mt < 4; ++mt)
#pragma unroll
        for (int nt = 0; nt < 4; ++nt)
#pragma unroll
            for (int r = 0; r < 4; ++r) acc[mt][nt][r] = 0.0f;

    const float* aPtr = A0 + (size_t)(by * BM + loadRow) * Kd + loadK;
    const float* wPtr = W0 + (size_t)(bx * BN + loadRow) * Kd + loadK;

    float4 ra0 = *(const float4*)(aPtr);
    float4 ra1 = *(const float4*)(aPtr + (size_t)64 * Kd);
    float4 rb0 = *(const float4*)(wPtr);
    float4 rb1 = *(const float4*)(wPtr + (size_t)64 * Kd);

    for (int kt = 0; kt < Kd; kt += BK) {
        __syncthreads();
        {
            const int r0 = loadRow * SSTR;
            const int r1 = (loadRow + 64) * SSTR;
            // hi = tf32_rna(x); lo = tf32_rna(x - float(hi))
            uint32_t h;
            float hf;
#define SPLIT_STORE(ARRH, ARRL, ROW, D, X)                                \
            h = f2tf32(X); hf = __uint_as_float(h);                       \
            ARRH[(ROW) + (D)] = h; ARRL[(ROW) + (D)] = f2tf32((X) - hf);
            SPLIT_STORE(Ahi, Alo, r0, d0, ra0.x)
            SPLIT_STORE(Ahi, Alo, r0, d1, ra0.y)
            SPLIT_STORE(Ahi, Alo, r0, d2, ra0.z)
            SPLIT_STORE(Ahi, Alo, r0, d3, ra0.w)
            SPLIT_STORE(Ahi, Alo, r1, d0, ra1.x)
            SPLIT_STORE(Ahi, Alo, r1, d1, ra1.y)
            SPLIT_STORE(Ahi, Alo, r1, d2, ra1.z)
            SPLIT_STORE(Ahi, Alo, r1, d3, ra1.w)
            SPLIT_STORE(Bhi, Blo, r0, d0, rb0.x)
            SPLIT_STORE(Bhi, Blo, r0, d1, rb0.y)
            SPLIT_STORE(Bhi, Blo, r0, d2, rb0.z)
            SPLIT_STORE(Bhi, Blo, r0, d3, rb0.w)
            SPLIT_STORE(Bhi, Blo, r1, d0, rb1.x)
            SPLIT_STORE(Bhi, Blo, r1, d1, rb1.y)
            SPLIT_STORE(Bhi, Blo, r1, d2, rb1.z)
            SPLIT_STORE(Bhi, Blo, r1, d3, rb1.w)
#undef SPLIT_STORE
        }
        __syncthreads();

        if (kt + BK < Kd) {
            aPtr += BK; wPtr += BK;
            ra0 = *(const float4*)(aPtr);
            ra1 = *(const float4*)(aPtr + (size_t)64 * Kd);
            rb0 = *(const float4*)(wPtr);
            rb1 = *(const float4*)(wPtr + (size_t)64 * Kd);
        }

#pragma unroll
        for (int ks = 0; ks < 2; ++ks) {
            const int kb = ks ? off1 : off0;
            uint2 bh[4], bl[4];
#pragma unroll
            for (int nt = 0; nt < 4; ++nt) {
                const int bidx = (wN * 32 + nt * 8 + g) * SSTR + kb;
                bh[nt] = *(const uint2*)&Bhi[bidx];
                bl[nt] = *(const uint2*)&Blo[bidx];
            }
#pragma unroll
            for (int mt = 0; mt < 4; ++mt) {
                const int r0 = (wM * 64 + mt * 16 + g) * SSTR + kb;
                const int r1 = r0 + 8 * SSTR;
                uint2 ah0 = *(const uint2*)&Ahi[r0];
                uint2 ah1 = *(const uint2*)&Ahi[r1];
                uint2 al0 = *(const uint2*)&Alo[r0];
                uint2 al1 = *(const uint2*)&Alo[r1];
#pragma unroll
                for (int nt = 0; nt < 4; ++nt) {
                    float* c = acc[mt][nt];
                    mma_tf32(c[0], c[1], c[2], c[3],
                             ah0.x, ah1.x, ah0.y, ah1.y, bh[nt].x, bh[nt].y);
                    mma_tf32(c[0], c[1], c[2], c[3],
                             ah0.x, ah1.x, ah0.y, ah1.y, bl[nt].x, bl[nt].y);
                    mma_tf32(c[0], c[1], c[2], c[3],
                             al0.x, al1.x, al0.y, al1.y, bh[nt].x, bh[nt].y);
                }
            }
        }
    }

    // ---- epilogue with suspect flagging ----
#pragma unroll
    for (int mt = 0; mt < 4; ++mt) {
#pragma unroll
        for (int nt = 0; nt < 4; ++nt) {
            const float* c = acc[mt][nt];
            const int row0 = by * BM + wM * 64 + mt * 16 + g;
            const int col  = bx * BN + wN * 32 + nt * 8 + 2 * q;
#pragma unroll
            for (int h = 0; h < 2; ++h) {
                const int row = row0 + 8 * h;
                const size_t idx = (size_t)row * Hd + col;
                float2 vv = *(const float2*)(vin + idx);
                float2 iv = *(const float2*)(iin + idx);
                float2 rv = *(const float2*)(rhoin + idx);
                float2 oz, ov, orh;
                lif_elem(vv.x, iv.x, rv.x, c[2 * h + 0], oz.x, ov.x, orh.x);
                lif_elem(vv.y, iv.y, rv.y, c[2 * h + 1], oz.y, ov.y, orh.y);
                *(float2*)(out_z   + idx) = oz;
                *(float2*)(out_v   + idx) = ov;
                *(float2*)(out_rho + idx) = orh;

                // suspect test: |v_dec - V_TH| < EPS
                float vd0 = (vv.x + DT_TAU_MEM * ((0.0f - vv.x) + iv.x)) + c[2 * h + 0];
                float vd1 = (vv.y + DT_TAU_MEM * ((0.0f - vv.y) + iv.y)) + c[2 * h + 1];
                if (fabsf(vd0 - V_TH_C) < EPS_FIX) {
                    int s = atomicAdd(&g_susp_count, 1);
                    if (s < MAX_SUSP) g_susp_list[s] = (int)idx;
                }
                if (fabsf(vd1 - V_TH_C) < EPS_FIX) {
                    int s = atomicAdd(&g_susp_count, 1);
                    if (s < MAX_SUSP) g_susp_list[s] = (int)(idx + 1);
                }
            }
        }
    }
}

// =============== K_fixup: exact recompute of flagged elements ================
__global__ void fixup_kernel(
    const float* __restrict__ vin, const float* __restrict__ gmat,
    const float* __restrict__ iin, const float* __restrict__ rhoin,
    float* __restrict__ out_z, float* __restrict__ out_v, float* __restrict__ out_rho)
{
    int n = g_susp_count;
    if (n > MAX_SUSP) n = MAX_SUSP;
    for (int s = blockIdx.x * blockDim.x + threadIdx.x; s < n;
         s += gridDim.x * blockDim.x) {
        const int e   = g_susp_list[s];
        const int row = e >> 11;       // Hd = 2048
        const int col = e & 2047;

        // exact serial ascending-k fp32 FMA chain (matches R1's 0-flip path)
        const float4* ar = (const float4*)(vin  + (size_t)row * Kd);
        const float4* br = (const float4*)(gmat + (size_t)col * Kd);
        float accv = 0.0f;
        for (int k4 = 0; k4 < Kd / 4; ++k4) {
            float4 a = ar[k4];
            float4 b = br[k4];
            accv = fmaf(a.x, b.x, accv);
            accv = fmaf(a.y, b.y, accv);
            accv = fmaf(a.z, b.z, accv);
            accv = fmaf(a.w, b.w, accv);
        }

        const size_t idx = (size_t)row * Hd + col;
        float z, vo, ro;
        lif_elem(vin[idx], iin[idx], rhoin[idx], accv, z, vo, ro);
        out_z[idx]   = z;
        out_v[idx]   = vo;
        out_rho[idx] = ro;
    }
}

// =============== K2: i-path TF32 MMA (R11 layout, 256 thr, standalone) =======
__global__ void __launch_bounds__(256, 2) ipath_kernel(
    const float* __restrict__ A0, const float* __restrict__ W0,
    const float* __restrict__ A1, const float* __restrict__ W1,
    const float* __restrict__ iin, float* __restrict__ out_i)
{
    __shared__ uint32_t Ahi[BM * SSTR];
    __shared__ uint32_t Bhi[BN * SSTR];

    const int bid = blockIdx.x;
    const int bx = bid & 15;
    const int by = bid >> 4;

    const int tid  = threadIdx.x;
    const int warp = tid >> 5;
    const int lane = tid & 31;
    const int g    = lane >> 2;
    const int q    = lane & 3;
    const int wM   = warp >> 2;
    const int wN   = warp & 3;

    const int loadRow = tid >> 2;
    const int loadK   = (tid & 3) << 2;
    const int t       = tid & 3;
    const int ta_     = t >> 1;
    const int tb_     = t & 1;

    const int d0 = (ta_ ? 10 : 0) + tb_;
    const int d1 = (ta_ ? 14 : 4) + tb_;
    const int d2 = (ta_ ?  8 : 2) + tb_;
    const int d3 = (ta_ ? 12 : 6) + tb_;

    const int B0q  = ((q & 1) << 2) | (q & 2);
    const int off0 = B0q;
    const int off1 = 8 + (B0q ^ 2);

    float acc[4][4][4];
#pragma unroll
    for (int mt = 0; mt < 4; ++mt)
#pragma unroll
        for (int nt = 0; nt < 4; ++nt)
#pragma unroll
            for (int r = 0; r < 4; ++r) acc[mt][nt][r] = 0.0f;

#pragma unroll
    for (int p = 0; p < 2; ++p) {
        const float* Amat = (p == 0) ? A0 : A1;
        const float* Wmat = (p == 0) ? W0 : W1;
        const float* aPtr = Amat + (size_t)(by * BM + loadRow) * Kd + loadK;
        const float* wPtr = Wmat + (size_t)(bx * BN + loadRow) * Kd + loadK;

        uint4 ra0 = *(const uint4*)(aPtr);
        uint4 ra1 = *(const uint4*)(aPtr + (size_t)64 * Kd);
        uint4 rb0 = *(const uint4*)(wPtr);
        uint4 rb1 = *(const uint4*)(wPtr + (size_t)64 * Kd);

        for (int kt = 0; kt < Kd; kt += BK) {
            __syncthreads();
            {
                const int r0 = loadRow * SSTR;
                const int r1 = (loadRow + 64) * SSTR;
                Ahi[r0 + d0] = ra0.x;
                Ahi[r0 + d1] = ra0.y;
                Ahi[r0 + d2] = ra0.z;
                Ahi[r0 + d3] = ra0.w;
                Ahi[r1 + d0] = ra1.x;
                Ahi[r1 + d1] = ra1.y;
                Ahi[r1 + d2] = ra1.z;
                Ahi[r1 + d3] = ra1.w;
                Bhi[r0 + d0] = rb0.x;
                Bhi[r0 + d1] = rb0.y;
                Bhi[r0 + d2] = rb0.z;
                Bhi[r0 + d3] = rb0.w;
                Bhi[r1 + d0] = rb1.x;
                Bhi[r1 + d1] = rb1.y;
                Bhi[r1 + d2] = rb1.z;
                Bhi[r1 + d3] = rb1.w;
            }
            __syncthreads();

            if (kt + BK < Kd) {
                aPtr += BK; wPtr += BK;
                ra0 = *(const uint4*)(aPtr);
                ra1 = *(const uint4*)(aPtr + (size_t)64 * Kd);
                rb0 = *(const uint4*)(wPtr);
                rb1 = *(const uint4*)(wPtr + (size_t)64 * Kd);
            }

#pragma unroll
            for (int ks = 0; ks < 2; ++ks) {
                const int kb = ks ? off1 : off0;
                uint2 bh[4];
#pragma unroll
                for (int nt = 0; nt < 4; ++nt)
                    bh[nt] = *(const uint2*)&Bhi[(wN * 32 + nt * 8 + g) * SSTR + kb];
#pragma unroll
                for (int mt = 0; mt < 4; ++mt) {
                    const int r0 = (wM * 64 + mt * 16 + g) * SSTR + kb;
                    uint2 tA = *(const uint2*)&Ahi[r0];
                    uint2 tC = *(const uint2*)&Ahi[r0 + 8 * SSTR];
#pragma unroll
                    for (int nt = 0; nt < 4; ++nt) {
                        float* c = acc[mt][nt];
                        mma_tf32(c[0], c[1], c[2], c[3],
                                 tA.x, tC.x, tA.y, tC.y, bh[nt].x, bh[nt].y);
                    }
                }
            }
        }
    }

#pragma unroll
    for (int mt = 0; mt < 4; ++mt) {
#pragma unroll
        for (int nt = 0; nt < 4; ++nt) {
            const float* c = acc[mt][nt];
            const int row0 = by * BM + wM * 64 + mt * 16 + g;
            const int col  = bx * BN + wN * 32 + nt * 8 + 2 * q;
            const size_t idx0 = (size_t)row0 * Hd + col;
            const size_t idx1 = idx0 + (size_t)8 * Hd;
            float2 i0 = *(const float2*)(iin + idx0);
            float2 i1 = *(const float2*)(iin + idx1);
            float2 o0, o1;
            o0.x = (i0.x - DT_TAU_SYN * i0.x) + c[0];
            o0.y = (i0.y - DT_TAU_SYN * i0.y) + c[1];
            o1.x = (i1.x - DT_TAU_SYN * i1.x) + c[2];
            o1.y = (i1.y - DT_TAU_SYN * i1.y) + c[3];
            *(float2*)(out_i + idx0) = o0;
            *(float2*)(out_i + idx1) = o1;
        }
    }
}

extern "C" void kernel_launch(void* const* d_in, const int* in_sizes, int n_in,
                              void* d_out, int out_size)
{
    const float* inp  = (const float*)d_in[0];
    const float* z    = (const float*)d_in[1];
    const float* v    = (const float*)d_in[2];
    const float* icur = (const float*)d_in[3];
    const float* rho  = (const float*)d_in[4];
    const float* Wi   = (const float*)d_in[5];
    const float* Wr   = (const float*)d_in[6];
    const float* g    = (const float*)d_in[7];

    float* out      = (float*)d_out;
    const size_t nBH = (size_t)Bd * Hd;
    float* out_z    = out;
    float* out_v    = out + nBH;
    float* out_i    = out + 2 * nBH;
    float* out_rho  = out + 3 * nBH;

    reset_kernel<<<1, 32>>>();
    coupling_tc_kernel<<<512, 256>>>(v, g, v, icur, rho, out_z, out_v, out_rho);
    ipath_kernel<<<512, 256>>>(inp, Wi, z, Wr, icur, out_i);
    fixup_kernel<<<256, 128>>>(v, g, icur, rho, out_z, out_v, out_rho);
}

// round 14
// speedup vs baseline: 1.2828x; 1.2828x over previous
#include <cuda_runtime.h>
#include <cstdint>

// LIF-MC-Refrac (R14): all-tensor, single-pass coupling + exact fixup.
//  K_reset  : zero suspect counter.
//  K1 coupling: SINGLE-pass RNA-tf32 mma.sync -> z,v,rho; flags |v_dec-1|<EPS.
//  K2 i-path : TF32 mma.sync (R11 layout) -> i.
//  K_fixup  : exact serial-k fp32 recompute of flagged elements (0-flip order).

namespace {
constexpr int Bd = 4096;
constexpr int Hd = 2048;
constexpr int Kd = 2048;

constexpr int BM = 128, BN = 128, BK = 16;
constexpr int SSTR = BK + 4;

constexpr float DT_TAU_MEM = 0.1f;
constexpr float DT_TAU_SYN = 0.2f;
constexpr float V_TH_C     = 1.0f;
constexpr float RHO_RST    = 5.0f;

constexpr float EPS_FIX    = 4e-3f;
constexpr int   MAX_SUSP   = 1 << 20;
}

__device__ int g_susp_count;
__device__ int g_susp_list[MAX_SUSP];

__device__ __forceinline__ uint32_t f2tf32(float x) {
    uint32_t r;
    asm("cvt.rna.tf32.f32 %0, %1;" : "=r"(r) : "f"(x));
    return r;
}

__device__ __forceinline__ void mma_tf32(float& c0, float& c1, float& c2, float& c3,
                                         uint32_t a0, uint32_t a1, uint32_t a2, uint32_t a3,
                                         uint32_t b0, uint32_t b1)
{
    asm volatile(
        "mma.sync.aligned.m16n8k8.row.col.f32.tf32.tf32.f32 "
        "{%0,%1,%2,%3},{%4,%5,%6,%7},{%8,%9},{%0,%1,%2,%3};"
        : "+f"(c0), "+f"(c1), "+f"(c2), "+f"(c3)
        : "r"(a0), "r"(a1), "r"(a2), "r"(a3), "r"(b0), "r"(b1));
}

__device__ __forceinline__ void lif_elem(float v, float i, float rho, float couple,
                                         float& z_out, float& v_out, float& rho_out)
{
    float dv    = DT_TAU_MEM * ((0.0f - v) + i);
    float v_dec = (v + dv) + couple;
    float z     = (v_dec - V_TH_C) > 0.0f ? 1.0f : 0.0f;
    float v_new = (1.0f - z) * v_dec;
    float mask  = rho > 0.0f ? 1.0f : 0.0f;
    v_new = (1.0f - mask) * v_new + mask * v;
    z     = (1.0f - mask) * z;
    rho_out = (1.0f - z) * fmaxf(rho - mask, 0.0f) + z * RHO_RST;
    z_out = z;
    v_out = v_new;
}

// =============== K_reset ======================================================
__global__ void reset_kernel() {
    if (threadIdx.x == 0) g_susp_count = 0;
}

// =============== K1: single-pass RNA-tf32 coupling + suspect flagging ========
// R11 conflict-free k-position map: pos(k)=2f(a,c)+b, f0=[0,2,1,3], f1=[5,7,4,6]
__global__ void __launch_bounds__(256, 2) coupling_tc_kernel(
    const float* __restrict__ A0, const float* __restrict__ W0,
    const float* __restrict__ vin, const float* __restrict__ iin,
    const float* __restrict__ rhoin,
    float* __restrict__ out_z, float* __restrict__ out_v, float* __restrict__ out_rho)
{
    __shared__ uint32_t Ahi[BM * SSTR];
    __shared__ uint32_t Bhi[BN * SSTR];

    const int bid = blockIdx.x;
    const int bx = bid & 15;
    const int by = bid >> 4;

    const int tid  = threadIdx.x;
    const int warp = tid >> 5;
    const int lane = tid & 31;
    const int g    = lane >> 2;
    const int q    = lane & 3;
    const int wM   = warp >> 2;
    const int wN   = warp & 3;

    const int loadRow = tid >> 2;
    const int loadK   = (tid & 3) << 2;
    const int t       = tid & 3;
    const int ta_     = t >> 1;
    const int tb_     = t & 1;

    const int d0 = (ta_ ? 10 : 0) + tb_;
    const int d1 = (ta_ ? 14 : 4) + tb_;
    const int d2 = (ta_ ?  8 : 2) + tb_;
    const int d3 = (ta_ ? 12 : 6) + tb_;

    const int B0q  = ((q & 1) << 2) | (q & 2);
    const int off0 = B0q;
    const int off1 = 8 + (B0q ^ 2);

    float acc[4][4][4];
#pragma unroll
    for (int mt = 0; mt < 4; ++mt)
#pragma unroll
        for (int nt = 0; nt < 4; ++nt)
#pragma unroll
            for (int r = 0; r < 4; ++r) acc[mt][nt][r] = 0.0f;

    const float* aPtr = A0 + (size_t)(by * BM + loadRow) * Kd + loadK;
    const float* wPtr = W0 + (size_t)(bx * BN + loadRow) * Kd + loadK;

    float4 ra0 = *(const float4*)(aPtr);
    float4 ra1 = *(const float4*)(aPtr + (size_t)64 * Kd);
    float4 rb0 = *(const float4*)(wPtr);
    float4 rb1 = *(const float4*)(wPtr + (size_t)64 * Kd);

    for (int kt = 0; kt < Kd; kt += BK) {
        __syncthreads();
        {
            const int r0 = loadRow * SSTR;
            const int r1 = (loadRow + 64) * SSTR;
            Ahi[r0 + d0] = f2tf32(ra0.x);
            Ahi[r0 + d1] = f2tf32(ra0.y);
            Ahi[r0 + d2] = f2tf32(ra0.z);
            Ahi[r0 + d3] = f2tf32(ra0.w);
            Ahi[r1 + d0] = f2tf32(ra1.x);
            Ahi[r1 + d1] = f2tf32(ra1.y);
            Ahi[r1 + d2] = f2tf32(ra1.z);
            Ahi[r1 + d3] = f2tf32(ra1.w);
            Bhi[r0 + d0] = f2tf32(rb0.x);
            Bhi[r0 + d1] = f2tf32(rb0.y);
            Bhi[r0 + d2] = f2tf32(rb0.z);
            Bhi[r0 + d3] = f2tf32(rb0.w);
            Bhi[r1 + d0] = f2tf32(rb1.x);
            Bhi[r1 + d1] = f2tf32(rb1.y);
            Bhi[r1 + d2] = f2tf32(rb1.z);
            Bhi[r1 + d3] = f2tf32(rb1.w);
        }
        __syncthreads();

        if (kt + BK < Kd) {
            aPtr += BK; wPtr += BK;
            ra0 = *(const float4*)(aPtr);
            ra1 = *(const float4*)(aPtr + (size_t)64 * Kd);
            rb0 = *(const float4*)(wPtr);
            rb1 = *(const float4*)(wPtr + (size_t)64 * Kd);
        }

#pragma unroll
        for (int ks = 0; ks < 2; ++ks) {
            const int kb = ks ? off1 : off0;
            uint2 bh[4];
#pragma unroll
            for (int nt = 0; nt < 4; ++nt)
                bh[nt] = *(const uint2*)&Bhi[(wN * 32 + nt * 8 + g) * SSTR + kb];
#pragma unroll
            for (int mt = 0; mt < 4; ++mt) {
                const int r0 = (wM * 64 + mt * 16 + g) * SSTR + kb;
                uint2 tA = *(const uint2*)&Ahi[r0];
                uint2 tC = *(const uint2*)&Ahi[r0 + 8 * SSTR];
#pragma unroll
                for (int nt = 0; nt < 4; ++nt) {
                    float* c = acc[mt][nt];
                    mma_tf32(c[0], c[1], c[2], c[3],
                             tA.x, tC.x, tA.y, tC.y, bh[nt].x, bh[nt].y);
                }
            }
        }
    }

    // ---- epilogue with suspect flagging ----
#pragma unroll
    for (int mt = 0; mt < 4; ++mt) {
#pragma unroll
        for (int nt = 0; nt < 4; ++nt) {
            const float* c = acc[mt][nt];
            const int row0 = by * BM + wM * 64 + mt * 16 + g;
            const int col  = bx * BN + wN * 32 + nt * 8 + 2 * q;
#pragma unroll
            for (int h = 0; h < 2; ++h) {
                const int row = row0 + 8 * h;
                const size_t idx = (size_t)row * Hd + col;
                float2 vv = *(const float2*)(vin + idx);
                float2 iv = *(const float2*)(iin + idx);
                float2 rv = *(const float2*)(rhoin + idx);
                float2 oz, ov, orh;
                lif_elem(vv.x, iv.x, rv.x, c[2 * h + 0], oz.x, ov.x, orh.x);
                lif_elem(vv.y, iv.y, rv.y, c[2 * h + 1], oz.y, ov.y, orh.y);
                *(float2*)(out_z   + idx) = oz;
                *(float2*)(out_v   + idx) = ov;
                *(float2*)(out_rho + idx) = orh;

                float vd0 = (vv.x + DT_TAU_MEM * ((0.0f - vv.x) + iv.x)) + c[2 * h + 0];
                float vd1 = (vv.y + DT_TAU_MEM * ((0.0f - vv.y) + iv.y)) + c[2 * h + 1];
                if (fabsf(vd0 - V_TH_C) < EPS_FIX) {
                    int s = atomicAdd(&g_susp_count, 1);
                    if (s < MAX_SUSP) g_susp_list[s] = (int)idx;
                }
                if (fabsf(vd1 - V_TH_C) < EPS_FIX) {
                    int s = atomicAdd(&g_susp_count, 1);
                    if (s < MAX_SUSP) g_susp_list[s] = (int)(idx + 1);
                }
            }
        }
    }
}

// =============== K_fixup: exact recompute, double-buffered ====================
__global__ void __launch_bounds__(128) fixup_kernel(
    const float* __restrict__ vin, const float* __restrict__ gmat,
    const float* __restrict__ iin, const float* __restrict__ rhoin,
    float* __restrict__ out_z, float* __restrict__ out_v, float* __restrict__ out_rho)
{
    int n = g_susp_count;
    if (n > MAX_SUSP) n = MAX_SUSP;
    for (int s = blockIdx.x * blockDim.x + threadIdx.x; s < n;
         s += gridDim.x * blockDim.x) {
        const int e   = g_susp_list[s];
        const int row = e >> 11;       // Hd = 2048
        const int col = e & 2047;

        const float4* ar = (const float4*)(vin  + (size_t)row * Kd);
        const float4* br = (const float4*)(gmat + (size_t)col * Kd);

        // double-buffered chunks of 4 float4 (16 values); serial ascending-k FMA
        float4 Ab[2][4], Bb[2][4];
#pragma unroll
        for (int j = 0; j < 4; ++j) { Ab[0][j] = ar[j]; Bb[0][j] = br[j]; }

        float accv = 0.0f;
        const int NCH = Kd / 16;       // 128 chunks
        for (int ch = 0; ch < NCH; ++ch) {
            const int cur = ch & 1, nxt = cur ^ 1;
            if (ch + 1 < NCH) {
#pragma unroll
                for (int j = 0; j < 4; ++j) {
                    Ab[nxt][j] = ar[(ch + 1) * 4 + j];
                    Bb[nxt][j] = br[(ch + 1) * 4 + j];
                }
            }
#pragma unroll
            for (int j = 0; j < 4; ++j) {
                float4 a = Ab[cur][j], b = Bb[cur][j];
                accv = fmaf(a.x, b.x, accv);
                accv = fmaf(a.y, b.y, accv);
                accv = fmaf(a.z, b.z, accv);
                accv = fmaf(a.w, b.w, accv);
            }
        }

        const size_t idx = (size_t)row * Hd + col;
        float z, vo, ro;
        lif_elem(vin[idx], iin[idx], rhoin[idx], accv, z, vo, ro);
        out_z[idx]   = z;
        out_v[idx]   = vo;
        out_rho[idx] = ro;
    }
}

// =============== K2: i-path TF32 MMA (R11/R13 layout, unchanged) =============
__global__ void __launch_bounds__(256, 2) ipath_kernel(
    const float* __restrict__ A0, const float* __restrict__ W0,
    const float* __restrict__ A1, const float* __restrict__ W1,
    const float* __restrict__ iin, float* __restrict__ out_i)
{
    __shared__ uint32_t Ahi[BM * SSTR];
    __shared__ uint32_t Bhi[BN * SSTR];

    const int bid = blockIdx.x;
    const int bx = bid & 15;
    const int by = bid >> 4;

    const int tid  = threadIdx.x;
    const int warp = tid >> 5;
    const int lane = tid & 31;
    const int g    = lane >> 2;
    const int q    = lane & 3;
    const int wM   = warp >> 2;
    const int wN   = warp & 3;

    const int loadRow = tid >> 2;
    const int loadK   = (tid & 3) << 2;
    const int t       = tid & 3;
    const int ta_     = t >> 1;
    const int tb_     = t & 1;

    const int d0 = (ta_ ? 10 : 0) + tb_;
    const int d1 = (ta_ ? 14 : 4) + tb_;
    const int d2 = (ta_ ?  8 : 2) + tb_;
    const int d3 = (ta_ ? 12 : 6) + tb_;

    const int B0q  = ((q & 1) << 2) | (q & 2);
    const int off0 = B0q;
    const int off1 = 8 + (B0q ^ 2);

    float acc[4][4][4];
#pragma unroll
    for (int mt = 0; mt < 4; ++mt)
#pragma unroll
        for (int nt = 0; nt < 4; ++nt)
#pragma unroll
            for (int r = 0; r < 4; ++r) acc[mt][nt][r] = 0.0f;

#pragma unroll
    for (int p = 0; p < 2; ++p) {
        const float* Amat = (p == 0) ? A0 : A1;
        const float* Wmat = (p == 0) ? W0 : W1;
        const float* aPtr = Amat + (size_t)(by * BM + loadRow) * Kd + loadK;
        const float* wPtr = Wmat + (size_t)(bx * BN + loadRow) * Kd + loadK;

        uint4 ra0 = *(const uint4*)(aPtr);
        uint4 ra1 = *(const uint4*)(aPtr + (size_t)64 * Kd);
        uint4 rb0 = *(const uint4*)(wPtr);
        uint4 rb1 = *(const uint4*)(wPtr + (size_t)64 * Kd);

        for (int kt = 0; kt < Kd; kt += BK) {
            __syncthreads();
            {
                const int r0 = loadRow * SSTR;
                const int r1 = (loadRow + 64) * SSTR;
                Ahi[r0 + d0] = ra0.x;
                Ahi[r0 + d1] = ra0.y;
                Ahi[r0 + d2] = ra0.z;
                Ahi[r0 + d3] = ra0.w;
                Ahi[r1 + d0] = ra1.x;
                Ahi[r1 + d1] = ra1.y;
                Ahi[r1 + d2] = ra1.z;
                Ahi[r1 + d3] = ra1.w;
                Bhi[r0 + d0] = rb0.x;
                Bhi[r0 + d1] = rb0.y;
                Bhi[r0 + d2] = rb0.z;
                Bhi[r0 + d3] = rb0.w;
                Bhi[r1 + d0] = rb1.x;
                Bhi[r1 + d1] = rb1.y;
                Bhi[r1 + d2] = rb1.z;
                Bhi[r1 + d3] = rb1.w;
            }
            __syncthreads();

            if (kt + BK < Kd) {
                aPtr += BK; wPtr += BK;
                ra0 = *(const uint4*)(aPtr);
                ra1 = *(const uint4*)(aPtr + (size_t)64 * Kd);
                rb0 = *(const uint4*)(wPtr);
                rb1 = *(const uint4*)(wPtr + (size_t)64 * Kd);
            }

#pragma unroll
            for (int ks = 0; ks < 2; ++ks) {
                const int kb = ks ? off1 : off0;
                uint2 bh[4];
#pragma unroll
                for (int nt = 0; nt < 4; ++nt)
                    bh[nt] = *(const uint2*)&Bhi[(wN * 32 + nt * 8 + g) * SSTR + kb];
#pragma unroll
                for (int mt = 0; mt < 4; ++mt) {
                    const int r0 = (wM * 64 + mt * 16 + g) * SSTR + kb;
                    uint2 tA = *(const uint2*)&Ahi[r0];
                    uint2 tC = *(const uint2*)&Ahi[r0 + 8 * SSTR];
#pragma unroll
                    for (int nt = 0; nt < 4; ++nt) {
                        float* c = acc[mt][nt];
                        mma_tf32(c[0], c[1], c[2], c[3],
                                 tA.x, tC.x, tA.y, tC.y, bh[nt].x, bh[nt].y);
                    }
                }
            }
        }
    }

#pragma unroll
    for (int mt = 0; mt < 4; ++mt) {
#pragma unroll
        for (int nt = 0; nt < 4; ++nt) {
            const float* c = acc[mt][nt];
            const int row0 = by * BM + wM * 64 + mt * 16 + g;
            const int col  = bx * BN + wN * 32 + nt * 8 + 2 * q;
            const size_t idx0 = (size_t)row0 * Hd + col;
            const size_t idx1 = idx0 + (size_t)8 * Hd;
            float2 i0 = *(const float2*)(iin + idx0);
            float2 i1 = *(const float2*)(iin + idx1);
            float2 o0, o1;
            o0.x = (i0.x - DT_TAU_SYN * i0.x) + c[0];
            o0.y = (i0.y - DT_TAU_SYN * i0.y) + c[1];
            o1.x = (i1.x - DT_TAU_SYN * i1.x) + c[2];
            o1.y = (i1.y - DT_TAU_SYN * i1.y) + c[3];
            *(float2*)(out_i + idx0) = o0;
            *(float2*)(out_i + idx1) = o1;
        }
    }
}

extern "C" void kernel_launch(void* const* d_in, const int* in_sizes, int n_in,
                              void* d_out, int out_size)
{
    const float* inp  = (const float*)d_in[0];
    const float* z    = (const float*)d_in[1];
    const float* v    = (const float*)d_in[2];
    const float* icur = (const float*)d_in[3];
    const float* rho  = (const float*)d_in[4];
    const float* Wi   = (const float*)d_in[5];
    const float* Wr   = (const float*)d_in[6];
    const float* g    = (const float*)d_in[7];

    float* out      = (float*)d_out;
    const size_t nBH = (size_t)Bd * Hd;
    float* out_z    = out;
    float* out_v    = out + nBH;
    float* out_i    = out + 2 * nBH;
    float* out_rho  = out + 3 * nBH;

    reset_kernel<<<1, 32>>>();
    coupling_tc_kernel<<<512, 256>>>(v, g, v, icur, rho, out_z, out_v, out_rho);
    ipath_kernel<<<512, 256>>>(inp, Wi, z, Wr, icur, out_i);
    fixup_kernel<<<1024, 128>>>(v, g, icur, rho, out_z, out_v, out_rho);
}

// round 15
// speedup vs baseline: 1.4413x; 1.1236x over previous
#include <cuda_runtime.h>
#include <cstdint>

// LIF-MC-Refrac (R15):
//  K_reset   : zero suspect counter.
//  K1 coupling: single-pass RNA-tf32 mma.sync, double-buffered smem (1 sync/tile)
//              -> z,v,rho; flags |v_dec-1|<EPS suspects.
//  K2 merged : bid<512 -> i-path TF32 MMA (double-buffered); bid>=512 -> exact
//              fixup of suspects (R14 serial-k order, unroll-8 load batching),
//              running on otherwise-idle second-wave SMs.

namespace {
constexpr int Bd = 4096;
constexpr int Hd = 2048;
constexpr int Kd = 2048;

constexpr int BM = 128, BN = 128, BK = 16;
constexpr int SSTR = BK + 4;
constexpr int TILEW = BM * SSTR;        // words per tile buffer (2560)

constexpr float DT_TAU_MEM = 0.1f;
constexpr float DT_TAU_SYN = 0.2f;
constexpr float V_TH_C     = 1.0f;
constexpr float RHO_RST    = 5.0f;

constexpr float EPS_FIX    = 4e-3f;
constexpr int   MAX_SUSP   = 1 << 20;

constexpr int IPATH_BLKS = 512;
constexpr int FIX_BLKS   = 128;
}

__device__ int g_susp_count;
__device__ int g_susp_list[MAX_SUSP];

__device__ __forceinline__ uint32_t f2tf32(float x) {
    uint32_t r;
    asm("cvt.rna.tf32.f32 %0, %1;" : "=r"(r) : "f"(x));
    return r;
}

__device__ __forceinline__ void mma_tf32(float& c0, float& c1, float& c2, float& c3,
                                         uint32_t a0, uint32_t a1, uint32_t a2, uint32_t a3,
                                         uint32_t b0, uint32_t b1)
{
    asm volatile(
        "mma.sync.aligned.m16n8k8.row.col.f32.tf32.tf32.f32 "
        "{%0,%1,%2,%3},{%4,%5,%6,%7},{%8,%9},{%0,%1,%2,%3};"
        : "+f"(c0), "+f"(c1), "+f"(c2), "+f"(c3)
        : "r"(a0), "r"(a1), "r"(a2), "r"(a3), "r"(b0), "r"(b1));
}

__device__ __forceinline__ void lif_elem(float v, float i, float rho, float couple,
                                         float& z_out, float& v_out, float& rho_out)
{
    float dv    = DT_TAU_MEM * ((0.0f - v) + i);
    float v_dec = (v + dv) + couple;
    float z     = (v_dec - V_TH_C) > 0.0f ? 1.0f : 0.0f;
    float v_new = (1.0f - z) * v_dec;
    float mask  = rho > 0.0f ? 1.0f : 0.0f;
    v_new = (1.0f - mask) * v_new + mask * v;
    z     = (1.0f - mask) * z;
    rho_out = (1.0f - z) * fmaxf(rho - mask, 0.0f) + z * RHO_RST;
    z_out = z;
    v_out = v_new;
}

// =============== K_reset ======================================================
__global__ void reset_kernel() {
    if (threadIdx.x == 0) g_susp_count = 0;
}

// =============== K1: single-pass tf32 coupling, double-buffered ==============
__global__ void __launch_bounds__(256, 2) coupling_tc_kernel(
    const float* __restrict__ A0, const float* __restrict__ W0,
    const float* __restrict__ vin, const float* __restrict__ iin,
    const float* __restrict__ rhoin,
    float* __restrict__ out_z, float* __restrict__ out_v, float* __restrict__ out_rho)
{
    __shared__ uint32_t Ahi[2 * TILEW];
    __shared__ uint32_t Bhi[2 * TILEW];

    const int bid = blockIdx.x;
    const int bx = bid & 15;
    const int by = bid >> 4;

    const int tid  = threadIdx.x;
    const int warp = tid >> 5;
    const int lane = tid & 31;
    const int g    = lane >> 2;
    const int q    = lane & 3;
    const int wM   = warp >> 2;
    const int wN   = warp & 3;

    const int loadRow = tid >> 2;
    const int loadK   = (tid & 3) << 2;
    const int t       = tid & 3;
    const int ta_     = t >> 1;
    const int tb_     = t & 1;

    const int d0 = (ta_ ? 10 : 0) + tb_;
    const int d1 = (ta_ ? 14 : 4) + tb_;
    const int d2 = (ta_ ?  8 : 2) + tb_;
    const int d3 = (ta_ ? 12 : 6) + tb_;

    const int B0q  = ((q & 1) << 2) | (q & 2);
    const int off0 = B0q;
    const int off1 = 8 + (B0q ^ 2);

    float acc[4][4][4];
#pragma unroll
    for (int mt = 0; mt < 4; ++mt)
#pragma unroll
        for (int nt = 0; nt < 4; ++nt)
#pragma unroll
            for (int r = 0; r < 4; ++r) acc[mt][nt][r] = 0.0f;

    const float* aPtr = A0 + (size_t)(by * BM + loadRow) * Kd + loadK;
    const float* wPtr = W0 + (size_t)(bx * BN + loadRow) * Kd + loadK;

    float4 ra0 = *(const float4*)(aPtr);
    float4 ra1 = *(const float4*)(aPtr + (size_t)64 * Kd);
    float4 rb0 = *(const float4*)(wPtr);
    float4 rb1 = *(const float4*)(wPtr + (size_t)64 * Kd);

    const int r0s = loadRow * SSTR;
    const int r1s = (loadRow + 64) * SSTR;

    for (int kt = 0, j = 0; kt < Kd; kt += BK, ++j) {
        uint32_t* Ab = Ahi + (j & 1) * TILEW;
        uint32_t* Bb = Bhi + (j & 1) * TILEW;

        Ab[r0s + d0] = f2tf32(ra0.x);
        Ab[r0s + d1] = f2tf32(ra0.y);
        Ab[r0s + d2] = f2tf32(ra0.z);
        Ab[r0s + d3] = f2tf32(ra0.w);
        Ab[r1s + d0] = f2tf32(ra1.x);
        Ab[r1s + d1] = f2tf32(ra1.y);
        Ab[r1s + d2] = f2tf32(ra1.z);
        Ab[r1s + d3] = f2tf32(ra1.w);
        Bb[r0s + d0] = f2tf32(rb0.x);
        Bb[r0s + d1] = f2tf32(rb0.y);
        Bb[r0s + d2] = f2tf32(rb0.z);
        Bb[r0s + d3] = f2tf32(rb0.w);
        Bb[r1s + d0] = f2tf32(rb1.x);
        Bb[r1s + d1] = f2tf32(rb1.y);
        Bb[r1s + d2] = f2tf32(rb1.z);
        Bb[r1s + d3] = f2tf32(rb1.w);
        __syncthreads();

        if (kt + BK < Kd) {
            aPtr += BK; wPtr += BK;
            ra0 = *(const float4*)(aPtr);
            ra1 = *(const float4*)(aPtr + (size_t)64 * Kd);
            rb0 = *(const float4*)(wPtr);
            rb1 = *(const float4*)(wPtr + (size_t)64 * Kd);
        }

#pragma unroll
        for (int ks = 0; ks < 2; ++ks) {
            const int kb = ks ? off1 : off0;
            uint2 bh[4];
#pragma unroll
            for (int nt = 0; nt < 4; ++nt)
                bh[nt] = *(const uint2*)&Bb[(wN * 32 + nt * 8 + g) * SSTR + kb];
#pragma unroll
            for (int mt = 0; mt < 4; ++mt) {
                const int r0 = (wM * 64 + mt * 16 + g) * SSTR + kb;
                uint2 tA = *(const uint2*)&Ab[r0];
                uint2 tC = *(const uint2*)&Ab[r0 + 8 * SSTR];
#pragma unroll
                for (int nt = 0; nt < 4; ++nt) {
                    float* c = acc[mt][nt];
                    mma_tf32(c[0], c[1], c[2], c[3],
                             tA.x, tC.x, tA.y, tC.y, bh[nt].x, bh[nt].y);
                }
            }
        }
    }

    // ---- epilogue with suspect flagging ----
#pragma unroll
    for (int mt = 0; mt < 4; ++mt) {
#pragma unroll
        for (int nt = 0; nt < 4; ++nt) {
            const float* c = acc[mt][nt];
            const int row0 = by * BM + wM * 64 + mt * 16 + g;
            const int col  = bx * BN + wN * 32 + nt * 8 + 2 * q;
#pragma unroll
            for (int h = 0; h < 2; ++h) {
                const int row = row0 + 8 * h;
                const size_t idx = (size_t)row * Hd + col;
                float2 vv = *(const float2*)(vin + idx);
                float2 iv = *(const float2*)(iin + idx);
                float2 rv = *(const float2*)(rhoin + idx);
                float2 oz, ov, orh;
                lif_elem(vv.x, iv.x, rv.x, c[2 * h + 0], oz.x, ov.x, orh.x);
                lif_elem(vv.y, iv.y, rv.y, c[2 * h + 1], oz.y, ov.y, orh.y);
                *(float2*)(out_z   + idx) = oz;
                *(float2*)(out_v   + idx) = ov;
                *(float2*)(out_rho + idx) = orh;

                float vd0 = (vv.x + DT_TAU_MEM * ((0.0f - vv.x) + iv.x)) + c[2 * h + 0];
                float vd1 = (vv.y + DT_TAU_MEM * ((0.0f - vv.y) + iv.y)) + c[2 * h + 1];
                if (fabsf(vd0 - V_TH_C) < EPS_FIX) {
                    int s = atomicAdd(&g_susp_count, 1);
                    if (s < MAX_SUSP) g_susp_list[s] = (int)idx;
                }
                if (fabsf(vd1 - V_TH_C) < EPS_FIX) {
                    int s = atomicAdd(&g_susp_count, 1);
                    if (s < MAX_SUSP) g_susp_list[s] = (int)(idx + 1);
                }
            }
        }
    }
}

// =============== K2 merged: i-path MMA (bid<512) + fixup (bid>=512) ==========
__global__ void __launch_bounds__(256, 2) ipath_fix_kernel(
    const float* __restrict__ A0, const float* __restrict__ W0,
    const float* __restrict__ A1, const float* __restrict__ W1,
    const float* __restrict__ iin, float* __restrict__ out_i,
    const float* __restrict__ vin, const float* __restrict__ gmat,
    const float* __restrict__ rhoin,
    float* __restrict__ out_z, float* __restrict__ out_v, float* __restrict__ out_rho)
{
    __shared__ uint32_t Ahi[2 * TILEW];
    __shared__ uint32_t Bhi[2 * TILEW];

    const int bid = blockIdx.x;
    const int tid = threadIdx.x;

    if (bid >= IPATH_BLKS) {
        // ----------------- fixup role -----------------
        int n = g_susp_count;
        if (n > MAX_SUSP) n = MAX_SUSP;
        for (int s = (bid - IPATH_BLKS) * 256 + tid; s < n; s += FIX_BLKS * 256) {
            const int e   = g_susp_list[s];
            const int row = e >> 11;     // Hd = 2048
            const int col = e & 2047;

            const float4* ar = (const float4*)(vin  + (size_t)row * Kd);
            const float4* br = (const float4*)(gmat + (size_t)col * Kd);
            float accv = 0.0f;
#pragma unroll 8
            for (int k4 = 0; k4 < Kd / 4; ++k4) {
                float4 a = ar[k4];
                float4 b = br[k4];
                accv = fmaf(a.x, b.x, accv);
                accv = fmaf(a.y, b.y, accv);
                accv = fmaf(a.z, b.z, accv);
                accv = fmaf(a.w, b.w, accv);
            }

            const size_t idx = (size_t)row * Hd + col;
            float z, vo, ro;
            lif_elem(vin[idx], iin[idx], rhoin[idx], accv, z, vo, ro);
            out_z[idx]   = z;
            out_v[idx]   = vo;
            out_rho[idx] = ro;
        }
        return;
    }

    // ----------------- i-path MMA role -----------------
    const int bx = bid & 15;
    const int by = bid >> 4;

    const int warp = tid >> 5;
    const int lane = tid & 31;
    const int g    = lane >> 2;
    const int q    = lane & 3;
    const int wM   = warp >> 2;
    const int wN   = warp & 3;

    const int loadRow = tid >> 2;
    const int loadK   = (tid & 3) << 2;
    const int t       = tid & 3;
    const int ta_     = t >> 1;
    const int tb_     = t & 1;

    const int d0 = (ta_ ? 10 : 0) + tb_;
    const int d1 = (ta_ ? 14 : 4) + tb_;
    const int d2 = (ta_ ?  8 : 2) + tb_;
    const int d3 = (ta_ ? 12 : 6) + tb_;

    const int B0q  = ((q & 1) << 2) | (q & 2);
    const int off0 = B0q;
    const int off1 = 8 + (B0q ^ 2);

    float acc[4][4][4];
#pragma unroll
    for (int mt = 0; mt < 4; ++mt)
#pragma unroll
        for (int nt = 0; nt < 4; ++nt)
#pragma unroll
            for (int r = 0; r < 4; ++r) acc[mt][nt][r] = 0.0f;

    const int r0s = loadRow * SSTR;
    const int r1s = (loadRow + 64) * SSTR;

#pragma unroll
    for (int p = 0; p < 2; ++p) {
        const float* Amat = (p == 0) ? A0 : A1;
        const float* Wmat = (p == 0) ? W0 : W1;
        const float* aPtr = Amat + (size_t)(by * BM + loadRow) * Kd + loadK;
        const float* wPtr = Wmat + (size_t)(bx * BN + loadRow) * Kd + loadK;

        uint4 ra0 = *(const uint4*)(aPtr);
        uint4 ra1 = *(const uint4*)(aPtr + (size_t)64 * Kd);
        uint4 rb0 = *(const uint4*)(wPtr);
        uint4 rb1 = *(const uint4*)(wPtr + (size_t)64 * Kd);

        for (int kt = 0, j = 0; kt < Kd; kt += BK, ++j) {
            uint32_t* Ab = Ahi + (j & 1) * TILEW;
            uint32_t* Bb = Bhi + (j & 1) * TILEW;

            Ab[r0s + d0] = ra0.x;
            Ab[r0s + d1] = ra0.y;
            Ab[r0s + d2] = ra0.z;
            Ab[r0s + d3] = ra0.w;
            Ab[r1s + d0] = ra1.x;
            Ab[r1s + d1] = ra1.y;
            Ab[r1s + d2] = ra1.z;
            Ab[r1s + d3] = ra1.w;
            Bb[r0s + d0] = rb0.x;
            Bb[r0s + d1] = rb0.y;
            Bb[r0s + d2] = rb0.z;
            Bb[r0s + d3] = rb0.w;
            Bb[r1s + d0] = rb1.x;
            Bb[r1s + d1] = rb1.y;
            Bb[r1s + d2] = rb1.z;
            Bb[r1s + d3] = rb1.w;
            __syncthreads();

            if (kt + BK < Kd) {
                aPtr += BK; wPtr += BK;
                ra0 = *(const uint4*)(aPtr);
                ra1 = *(const uint4*)(aPtr + (size_t)64 * Kd);
                rb0 = *(const uint4*)(wPtr);
                rb1 = *(const uint4*)(wPtr + (size_t)64 * Kd);
            }

#pragma unroll
            for (int ks = 0; ks < 2; ++ks) {
                const int kb = ks ? off1 : off0;
                uint2 bh[4];
#pragma unroll
                for (int nt = 0; nt < 4; ++nt)
                    bh[nt] = *(const uint2*)&Bb[(wN * 32 + nt * 8 + g) * SSTR + kb];
#pragma unroll
                for (int mt = 0; mt < 4; ++mt) {
                    const int r0 = (wM * 64 + mt * 16 + g) * SSTR + kb;
                    uint2 tA = *(const uint2*)&Ab[r0];
                    uint2 tC = *(const uint2*)&Ab[r0 + 8 * SSTR];
#pragma unroll
                    for (int nt = 0; nt < 4; ++nt) {
                        float* c = acc[mt][nt];
                        mma_tf32(c[0], c[1], c[2], c[3],
                                 tA.x, tC.x, tA.y, tC.y, bh[nt].x, bh[nt].y);
                    }
                }
            }
        }
        // buffers alternate across p as well since j restarts — force a sync so
        // the next p's first STS (buffer 0) doesn't race this p's last MMA read
        // (buffer (128-1)&1 = 1; first write of next p hits buffer 0, last read
        //  of buffer 0 was tile 126 — already fenced by tile 127's sync). Safe.
    }

#pragma unroll
    for (int mt = 0; mt < 4; ++mt) {
#pragma unroll
        for (int nt = 0; nt < 4; ++nt) {
            const float* c = acc[mt][nt];
            const int row0 = by * BM + wM * 64 + mt * 16 + g;
            const int col  = bx * BN + wN * 32 + nt * 8 + 2 * q;
            const size_t idx0 = (size_t)row0 * Hd + col;
            const size_t idx1 = idx0 + (size_t)8 * Hd;
            float2 i0 = *(const float2*)(iin + idx0);
            float2 i1 = *(const float2*)(iin + idx1);
            float2 o0, o1;
            o0.x = (i0.x - DT_TAU_SYN * i0.x) + c[0];
            o0.y = (i0.y - DT_TAU_SYN * i0.y) + c[1];
            o1.x = (i1.x - DT_TAU_SYN * i1.x) + c[2];
            o1.y = (i1.y - DT_TAU_SYN * i1.y) + c[3];
            *(float2*)(out_i + idx0) = o0;
            *(float2*)(out_i + idx1) = o1;
        }
    }
}

extern "C" void kernel_launch(void* const* d_in, const int* in_sizes, int n_in,
                              void* d_out, int out_size)
{
    const float* inp  = (const float*)d_in[0];
    const float* z    = (const float*)d_in[1];
    const float* v    = (const float*)d_in[2];
    const float* icur = (const float*)d_in[3];
    const float* rho  = (const float*)d_in[4];
    const float* Wi   = (const float*)d_in[5];
    const float* Wr   = (const float*)d_in[6];
    const float* g    = (const float*)d_in[7];

    float* out      = (float*)d_out;
    const size_t nBH = (size_t)Bd * Hd;
    float* out_z    = out;
    float* out_v    = out + nBH;
    float* out_i    = out + 2 * nBH;
    float* out_rho  = out + 3 * nBH;

    reset_kernel<<<1, 32>>>();
    coupling_tc_kernel<<<512, 256>>>(v, g, v, icur, rho, out_z, out_v, out_rho);
    ipath_fix_kernel<<<IPATH_BLKS + FIX_BLKS, 256>>>(
        inp, Wi, z, Wr, icur, out_i, v, g, rho, out_z, out_v, out_rho);
}